// round 16
// baseline (speedup 1.0000x reference)
#include <cuda_runtime.h>
#include <cuda_bf16.h>
#include <math.h>

#define BB   16
#define CC   256
#define CI   128
#define HWN  4096
#define NP   1024

__device__ unsigned d_xts[BB * HWN * CC];
__device__ unsigned d_qpack[BB * HWN * CI];
__device__ unsigned d_kpack[BB * NP * 128];
__device__ unsigned d_vpack[BB * NP * 128];
__device__ unsigned d_ypack[BB * HWN * CI];
__device__ float    d_wyT[BB * CC * HWN];
__device__ unsigned d_wth[CI * CC];
__device__ unsigned d_wph[CI * CC];
__device__ unsigned d_wg[CI * CC];
__device__ unsigned d_ww[CC * CI];
__device__ float d_bnp[2][512][256];
__device__ float d_mean[CC];
__device__ float d_rstd[CC];

__device__ __forceinline__ unsigned ftf(float x) {
    unsigned u; asm("cvt.rna.tf32.f32 %0,%1;" : "=r"(u) : "f"(x)); return u;
}
__device__ __forceinline__ void mma8(float* c, unsigned a0, unsigned a1, unsigned a2, unsigned a3,
                                     unsigned b0, unsigned b1) {
    asm volatile("mma.sync.aligned.m16n8k8.row.col.f32.tf32.tf32.f32 "
                 "{%0,%1,%2,%3},{%4,%5,%6,%7},{%8,%9},{%0,%1,%2,%3};"
                 : "+f"(c[0]), "+f"(c[1]), "+f"(c[2]), "+f"(c[3])
                 : "r"(a0), "r"(a1), "r"(a2), "r"(a3), "r"(b0), "r"(b1));
}
__device__ __forceinline__ void mma16(float* c, unsigned a0, unsigned a1, unsigned a2, unsigned a3,
                                      unsigned b0, unsigned b1) {
    asm volatile("mma.sync.aligned.m16n8k16.row.col.f32.bf16.bf16.f32 "
                 "{%0,%1,%2,%3},{%4,%5,%6,%7},{%8,%9},{%0,%1,%2,%3};"
                 : "+f"(c[0]), "+f"(c[1]), "+f"(c[2]), "+f"(c[3])
                 : "r"(a0), "r"(a1), "r"(a2), "r"(a3), "r"(b0), "r"(b1));
}
__device__ __forceinline__ void split_pair(float a, float b, unsigned &hi, unsigned &lo) {
    __nv_bfloat16 ha = __float2bfloat16_rn(a), hb = __float2bfloat16_rn(b);
    float ra = a - __bfloat162float(ha), rb = b - __bfloat162float(hb);
    __nv_bfloat162 hv; hv.x = ha; hv.y = hb;
    __nv_bfloat162 lv; lv.x = __float2bfloat16_rn(ra); lv.y = __float2bfloat16_rn(rb);
    hi = *(unsigned*)&hv; lo = *(unsigned*)&lv;
}
__device__ __forceinline__ unsigned s2u(const void* p) {
    return (unsigned)__cvta_generic_to_shared(p);
}
__device__ __forceinline__ void cp16(unsigned dst, const void* src) {
    asm volatile("cp.async.cg.shared.global [%0], [%1], 16;" :: "r"(dst), "l"(src) : "memory");
}

// ---- x[b][c][n] -> packed split-bf16, layout [b][n][c] ----
__global__ __launch_bounds__(256) void transpose_pack_k(const float* __restrict__ x,
                                                        unsigned* __restrict__ xts) {
    __shared__ float tl[32][33];
    const int b = blockIdx.z, c0 = blockIdx.y * 32, n0 = blockIdx.x * 32;
    const int tx = threadIdx.x & 31, ty = threadIdx.x >> 5;
    const float* xb = x + (size_t)b * CC * HWN;
#pragma unroll
    for (int i = 0; i < 4; ++i)
        tl[ty + 8 * i][tx] = xb[(size_t)(c0 + ty + 8 * i) * HWN + n0 + tx];
    __syncthreads();
    unsigned* xso = xts + (size_t)b * HWN * CC;
#pragma unroll
    for (int rep = 0; rep < 2; ++rep) {
        const int task = threadIdx.x + rep * 256;
        const int nl = task >> 4, p = task & 15;
        float f0 = tl[2 * p][nl], f1 = tl[2 * p + 1][nl];
        unsigned hi, lo;
        split_pair(f0, f1, hi, lo);
        *(uint2*)&xso[(size_t)(n0 + nl) * CC + c0 + 2 * p] = make_uint2(hi, lo);
    }
}

// ---- pack all 4 weight matrices ----
__global__ __launch_bounds__(256) void pack_w4_k(const float* __restrict__ w0,
                                                 const float* __restrict__ w1,
                                                 const float* __restrict__ w2,
                                                 const float* __restrict__ w3,
                                                 unsigned* __restrict__ o0,
                                                 unsigned* __restrict__ o1,
                                                 unsigned* __restrict__ o2,
                                                 unsigned* __restrict__ o3) {
    const int id = blockIdx.x * 256 + threadIdx.x;
    const int seg = id >> 14, loc = id & 16383;
    const float* s = (seg == 0) ? w0 : (seg == 1) ? w1 : (seg == 2) ? w2 : w3;
    unsigned* d = (seg == 0) ? o0 : (seg == 1) ? o1 : (seg == 2) ? o2 : o3;
    float2 v = *(const float2*)&s[2 * loc];
    unsigned hi, lo;
    split_pair(v.x, v.y, hi, lo);
    *(uint2*)&d[2 * loc] = make_uint2(hi, lo);
}

// ---- merged input convs: blockIdx.y = 0(theta),1(phi->kpack),2(g->vpack) ----
__global__ __launch_bounds__(256) void conv3_k(const unsigned* __restrict__ A,
                                               const unsigned* __restrict__ wq,
                                               const unsigned* __restrict__ wk,
                                               const unsigned* __restrict__ wv,
                                               const float* __restrict__ bq,
                                               const float* __restrict__ bk,
                                               const float* __restrict__ bv,
                                               unsigned* __restrict__ outq,
                                               unsigned* __restrict__ outk,
                                               unsigned* __restrict__ outv) {
    extern __shared__ unsigned smu[];
    unsigned* Abuf = smu;               // 2 x 128 x 40
    unsigned* Bbuf = smu + 2 * 5120;
    const int K = 256;
    const int b = blockIdx.z, mode = blockIdx.y;
    const int row0 = blockIdx.x * 128;
    const int tid = threadIdx.x, lane = tid & 31, wid = tid >> 5;
    const int g = lane >> 2, t = lane & 3;
    const int wm = (wid & 3) * 32, wn = (wid >> 2) * 64;
    const unsigned* Ag = A + (size_t)b * HWN * CC + (size_t)row0 * K;
    const unsigned* Bg = (mode == 0) ? wq : (mode == 1) ? wk : wv;
    const float* bias = (mode == 0) ? bq : (mode == 1) ? bk : bv;

    const unsigned aBase = s2u(Abuf), bBase = s2u(Bbuf);
    auto stage = [&](int c) {
        const unsigned ab = aBase + (unsigned)((c & 1) * 5120 * 4);
        const unsigned bb = bBase + (unsigned)((c & 1) * 5120 * 4);
        const unsigned* Ac = Ag + c * 32;
        const unsigned* Bc = Bg + c * 32;
#pragma unroll
        for (int i = 0; i < 4; ++i) {
            const int id = tid + i * 256;
            const int row = id >> 3, q = id & 7;
            cp16(ab + (unsigned)((row * 40 + q * 4) * 4), Ac + (size_t)row * K + q * 4);
            cp16(bb + (unsigned)((row * 40 + q * 4) * 4), Bc + (size_t)row * K + q * 4);
        }
        asm volatile("cp.async.commit_group;" ::: "memory");
    };

    float acc[2][8][4];
#pragma unroll
    for (int mt = 0; mt < 2; ++mt)
#pragma unroll
        for (int j = 0; j < 8; ++j)
#pragma unroll
            for (int q = 0; q < 4; ++q) acc[mt][j][q] = 0.f;

    stage(0);
    for (int c = 0; c < 8; ++c) {
        if (c + 1 < 8) {
            stage(c + 1);
            asm volatile("cp.async.wait_group 1;" ::: "memory");
        } else {
            asm volatile("cp.async.wait_group 0;" ::: "memory");
        }
        __syncthreads();
        const unsigned* Asu = Abuf + (c & 1) * 5120;
        const unsigned* Bsu = Bbuf + (c & 1) * 5120;
#pragma unroll
        for (int kk = 0; kk < 2; ++kk) {
            unsigned ah[2][4], al[2][4];
#pragma unroll
            for (int mt = 0; mt < 2; ++mt) {
                const int rb = (wm + mt * 16 + g) * 40 + kk * 16 + 2 * t;
                uint2 p0 = *(uint2*)&Asu[rb];
                uint2 p1 = *(uint2*)&Asu[rb + 8 * 40];
                uint2 p2 = *(uint2*)&Asu[rb + 8];
                uint2 p3 = *(uint2*)&Asu[rb + 8 * 40 + 8];
                ah[mt][0] = p0.x; al[mt][0] = p0.y;
                ah[mt][1] = p1.x; al[mt][1] = p1.y;
                ah[mt][2] = p2.x; al[mt][2] = p2.y;
                ah[mt][3] = p3.x; al[mt][3] = p3.y;
            }
#pragma unroll
            for (int j = 0; j < 8; ++j) {
                const int nb = (wn + 8 * j + g) * 40 + kk * 16 + 2 * t;
                uint2 q0 = *(uint2*)&Bsu[nb];
                uint2 q1 = *(uint2*)&Bsu[nb + 8];
#pragma unroll
                for (int mt = 0; mt < 2; ++mt) {
                    mma16(acc[mt][j], ah[mt][0], ah[mt][1], ah[mt][2], ah[mt][3], q0.x, q1.x);
                    mma16(acc[mt][j], ah[mt][0], ah[mt][1], ah[mt][2], ah[mt][3], q0.y, q1.y);
                    mma16(acc[mt][j], al[mt][0], al[mt][1], al[mt][2], al[mt][3], q0.x, q1.x);
                }
            }
        }
        __syncthreads();
    }

    if (mode == 0) {
        unsigned* Cp = outq + (size_t)b * HWN * CI;
#pragma unroll
        for (int mt = 0; mt < 2; ++mt)
#pragma unroll
            for (int j = 0; j < 8; ++j) {
                const int col = wn + 8 * j + 2 * t;
                float2 bvv = *(const float2*)&bias[col];
                const int r = row0 + wm + mt * 16 + g;
                unsigned hi, lo;
                split_pair(acc[mt][j][0] + bvv.x, acc[mt][j][1] + bvv.y, hi, lo);
                *(uint2*)&Cp[(size_t)r * CI + col] = make_uint2(hi, lo);
                split_pair(acc[mt][j][2] + bvv.x, acc[mt][j][3] + bvv.y, hi, lo);
                *(uint2*)&Cp[(size_t)(r + 8) * CI + col] = make_uint2(hi, lo);
            }
    } else {
        float* ts = (float*)smu;          // pitch 136 (conflict-free float4 pool reads)
#pragma unroll
        for (int mt = 0; mt < 2; ++mt)
#pragma unroll
            for (int j = 0; j < 8; ++j) {
                const int cl = wn + 8 * j + 2 * t;
                float2 bvv = *(const float2*)&bias[cl];
                float* r0p = &ts[(wm + mt * 16 + g) * 136 + cl];
                r0p[0] = acc[mt][j][0] + bvv.x;  r0p[1] = acc[mt][j][1] + bvv.y;
                float* r1p = r0p + 8 * 136;
                r1p[0] = acc[mt][j][2] + bvv.x;  r1p[1] = acc[mt][j][3] + bvv.y;
            }
        __syncthreads();
        const int ph = blockIdx.x;
        unsigned* Op = (mode == 1) ? outk : outv;
#pragma unroll
        for (int rep = 0; rep < 4; ++rep) {
            const int task = tid + rep * 256;
            const int mloc = task >> 5, kq = task & 31;
            const float* t0 = &ts[(2 * mloc) * 136 + kq * 4];
            float4 v0 = *(const float4*)t0;
            float4 v1 = *(const float4*)(t0 + 136);
            float4 v2 = *(const float4*)(t0 + 64 * 136);
            float4 v3 = *(const float4*)(t0 + 65 * 136);
            float4 rr;
            rr.x = fmaxf(fmaxf(v0.x, v1.x), fmaxf(v2.x, v3.x));
            rr.y = fmaxf(fmaxf(v0.y, v1.y), fmaxf(v2.y, v3.y));
            rr.z = fmaxf(fmaxf(v0.z, v1.z), fmaxf(v2.z, v3.z));
            rr.w = fmaxf(fmaxf(v0.w, v1.w), fmaxf(v2.w, v3.w));
            const int m = ph * 32 + mloc;
            if (mode == 1) {
                unsigned h0, l0, h1, l1;
                split_pair(rr.x, rr.y, h0, l0);
                split_pair(rr.z, rr.w, h1, l1);
                *(uint4*)&Op[((size_t)b * NP + m) * 128 + kq * 4] = make_uint4(h0, l0, h1, l1);
            } else {
                unsigned* ob = Op + (size_t)b * NP * 128;
                const int base = (m >> 3) * 1024 + kq * 32 + (m & 7);
                ob[base]      = ftf(rr.x);
                ob[base + 8]  = ftf(rr.y);
                ob[base + 16] = ftf(rr.z);
                ob[base + 24] = ftf(rr.w);
            }
        }
    }
}

// ---- W conv: K=128, transposed store + BN partials ----
__global__ __launch_bounds__(256) void wconv_k(const unsigned* __restrict__ A,
                                               const unsigned* __restrict__ B,
                                               const float* __restrict__ bias,
                                               float* __restrict__ C) {
    extern __shared__ unsigned smu[];
    unsigned* Abuf = smu;
    unsigned* Bbuf = smu + 2 * 5120;
    const int K = 128;
    const int b = blockIdx.z;
    const int row0 = blockIdx.x * 128, col0 = blockIdx.y * 128;
    const int tid = threadIdx.x, lane = tid & 31, wid = tid >> 5;
    const int g = lane >> 2, t = lane & 3;
    const int wm = (wid & 3) * 32, wn = (wid >> 2) * 64;
    const unsigned* Ag = A + (size_t)b * HWN * CI + (size_t)row0 * K;
    const unsigned* Bg = B + (size_t)col0 * K;

    const unsigned aBase = s2u(Abuf), bBase = s2u(Bbuf);
    auto stage = [&](int c) {
        const unsigned ab = aBase + (unsigned)((c & 1) * 5120 * 4);
        const unsigned bb = bBase + (unsigned)((c & 1) * 5120 * 4);
        const unsigned* Ac = Ag + c * 32;
        const unsigned* Bc = Bg + c * 32;
#pragma unroll
        for (int i = 0; i < 4; ++i) {
            const int id = tid + i * 256;
            const int row = id >> 3, q = id & 7;
            cp16(ab + (unsigned)((row * 40 + q * 4) * 4), Ac + (size_t)row * K + q * 4);
            cp16(bb + (unsigned)((row * 40 + q * 4) * 4), Bc + (size_t)row * K + q * 4);
        }
        asm volatile("cp.async.commit_group;" ::: "memory");
    };

    float acc[2][8][4];
#pragma unroll
    for (int mt = 0; mt < 2; ++mt)
#pragma unroll
        for (int j = 0; j < 8; ++j)
#pragma unroll
            for (int q = 0; q < 4; ++q) acc[mt][j][q] = 0.f;

    stage(0);
    for (int c = 0; c < 4; ++c) {
        if (c + 1 < 4) {
            stage(c + 1);
            asm volatile("cp.async.wait_group 1;" ::: "memory");
        } else {
            asm volatile("cp.async.wait_group 0;" ::: "memory");
        }
        __syncthreads();
        const unsigned* Asu = Abuf + (c & 1) * 5120;
        const unsigned* Bsu = Bbuf + (c & 1) * 5120;
#pragma unroll
        for (int kk = 0; kk < 2; ++kk) {
            unsigned ah[2][4], al[2][4];
#pragma unroll
            for (int mt = 0; mt < 2; ++mt) {
                const int rb = (wm + mt * 16 + g) * 40 + kk * 16 + 2 * t;
                uint2 p0 = *(uint2*)&Asu[rb];
                uint2 p1 = *(uint2*)&Asu[rb + 8 * 40];
                uint2 p2 = *(uint2*)&Asu[rb + 8];
                uint2 p3 = *(uint2*)&Asu[rb + 8 * 40 + 8];
                ah[mt][0] = p0.x; al[mt][0] = p0.y;
                ah[mt][1] = p1.x; al[mt][1] = p1.y;
                ah[mt][2] = p2.x; al[mt][2] = p2.y;
                ah[mt][3] = p3.x; al[mt][3] = p3.y;
            }
#pragma unroll
            for (int j = 0; j < 8; ++j) {
                const int nb = (wn + 8 * j + g) * 40 + kk * 16 + 2 * t;
                uint2 q0 = *(uint2*)&Bsu[nb];
                uint2 q1 = *(uint2*)&Bsu[nb + 8];
#pragma unroll
                for (int mt = 0; mt < 2; ++mt) {
                    mma16(acc[mt][j], ah[mt][0], ah[mt][1], ah[mt][2], ah[mt][3], q0.x, q1.x);
                    mma16(acc[mt][j], ah[mt][0], ah[mt][1], ah[mt][2], ah[mt][3], q0.y, q1.y);
                    mma16(acc[mt][j], al[mt][0], al[mt][1], al[mt][2], al[mt][3], q0.x, q1.x);
                }
            }
        }
        __syncthreads();
    }

    float* ts = (float*)smu;    // pitch 136
    float sj[8][2], s2j[8][2];
#pragma unroll
    for (int j = 0; j < 8; ++j)
        sj[j][0] = sj[j][1] = s2j[j][0] = s2j[j][1] = 0.f;
#pragma unroll
    for (int mt = 0; mt < 2; ++mt)
#pragma unroll
        for (int j = 0; j < 8; ++j) {
            const int cl = wn + 8 * j + 2 * t;
            float2 bvv = *(const float2*)&bias[col0 + cl];
            const int nl = wm + mt * 16 + g;
            float v0 = acc[mt][j][0] + bvv.x, v1 = acc[mt][j][1] + bvv.y;
            float v2 = acc[mt][j][2] + bvv.x, v3 = acc[mt][j][3] + bvv.y;
            ts[cl * 136 + nl]           = v0;
            ts[(cl + 1) * 136 + nl]     = v1;
            ts[cl * 136 + nl + 8]       = v2;
            ts[(cl + 1) * 136 + nl + 8] = v3;
            sj[j][0] += v0 + v2;  sj[j][1] += v1 + v3;
            s2j[j][0] += v0 * v0 + v2 * v2;
            s2j[j][1] += v1 * v1 + v3 * v3;
        }
#pragma unroll
    for (int off = 4; off <= 16; off <<= 1)
#pragma unroll
        for (int j = 0; j < 8; ++j) {
            sj[j][0] += __shfl_xor_sync(0xffffffffu, sj[j][0], off);
            sj[j][1] += __shfl_xor_sync(0xffffffffu, sj[j][1], off);
            s2j[j][0] += __shfl_xor_sync(0xffffffffu, s2j[j][0], off);
            s2j[j][1] += __shfl_xor_sync(0xffffffffu, s2j[j][1], off);
        }
    __syncthreads();
    float* Ct = C + (size_t)b * CC * HWN;
#pragma unroll
    for (int rep = 0; rep < 16; ++rep) {
        const int task = tid + rep * 256;
        const int co = task >> 5, nq = task & 31;
        float4 v = *(const float4*)&ts[co * 136 + nq * 4];
        *(float4*)&Ct[(size_t)(col0 + co) * HWN + row0 + nq * 4] = v;
    }
    __syncthreads();
    float* partS = (float*)smu;
    float* partS2 = partS + 512;
    if (g == 0) {
#pragma unroll
        for (int j = 0; j < 8; ++j) {
            const int cbase = (wid & 3) * 128 + wn + 8 * j + 2 * t;
            partS[cbase] = sj[j][0];     partS[cbase + 1] = sj[j][1];
            partS2[cbase] = s2j[j][0];   partS2[cbase + 1] = s2j[j][1];
        }
    }
    __syncthreads();
    if (tid < 128) {
        const int c = tid;
        float s = partS[c] + partS[128 + c] + partS[256 + c] + partS[384 + c];
        float s2 = partS2[c] + partS2[128 + c] + partS2[256 + c] + partS2[384 + c];
        const int p = b * 32 + blockIdx.x;
        d_bnp[0][p][col0 + c] = s;
        d_bnp[1][p][col0 + c] = s2;
    }
}

// ---- fused attention: KT=32, 2 CTAs/SM, K+V double-buffered, P in regs ----
// qlo pitch 72, pairs (p, p+4) adjacent -> LDS.64 loads.
__global__ __launch_bounds__(256, 2) void attn_k(const unsigned* __restrict__ qpk,
                                                 const unsigned* __restrict__ kpk,
                                                 const unsigned* __restrict__ vpk,
                                                 unsigned* __restrict__ y) {
    extern __shared__ float sm[];
    unsigned* ks  = (unsigned*)sm;       // 2 x 32 x 136 = 8704 words
    unsigned* vs  = ks + 8704;           // 2 x 4096 = 8192
    unsigned* qlo = vs + 8192;           // 128 x 72 = 9216  (total 26112 w = 102KB)
    const int b = blockIdx.y, n0 = blockIdx.x * 128;
    const int tid = threadIdx.x, lane = tid & 31, wid = tid >> 5;
    const int g = lane >> 2, t = lane & 3;
    const int wrow = wid * 16;
    const unsigned* kg = kpk + (size_t)b * NP * 128;
    const unsigned* vg = vpk + (size_t)b * NP * 128;

    unsigned qh[8][4];
    {
        const unsigned* q0p = qpk + (size_t)b * HWN * CI + (size_t)(n0 + wrow + g) * CI;
        const unsigned* q1p = q0p + 8 * CI;
#pragma unroll
        for (int kk = 0; kk < 8; ++kk) {
            uint2 u0 = *(const uint2*)&q0p[kk * 16 + 2 * t];
            uint2 u1 = *(const uint2*)&q1p[kk * 16 + 2 * t];
            uint2 u2 = *(const uint2*)&q0p[kk * 16 + 2 * t + 8];
            uint2 u3 = *(const uint2*)&q1p[kk * 16 + 2 * t + 8];
            qh[kk][0] = u0.x; qh[kk][1] = u1.x; qh[kk][2] = u2.x; qh[kk][3] = u3.x;
            // lo pairs (p, p+4) stored adjacent at [(row)*72 + (kk*4+t)*2]
            *(uint2*)&qlo[(wrow + g) * 72 + (kk * 4 + t) * 2]     = make_uint2(u0.y, u2.y);
            *(uint2*)&qlo[(wrow + g + 8) * 72 + (kk * 4 + t) * 2] = make_uint2(u1.y, u3.y);
        }
    }

    const unsigned ksBase = s2u(ks), vsBase = s2u(vs);
    auto stageKV = [&](int it) {
        const unsigned kb = ksBase + (unsigned)((it & 1) * 4352 * 4);
        const unsigned vb = vsBase + (unsigned)((it & 1) * 4096 * 4);
        const unsigned* kgt = kg + (size_t)it * 32 * 128;
        const unsigned* vgt = vg + (size_t)it * 4096;
#pragma unroll
        for (int i = 0; i < 4; ++i) {
            const int id = tid + i * 256;
            const int row = id >> 5, c = id & 31;
            cp16(kb + (unsigned)((row * 136 + c * 4) * 4), kgt + row * 128 + c * 4);
            cp16(vb + (unsigned)(id * 16), vgt + id * 4);
        }
        asm volatile("cp.async.commit_group;" ::: "memory");
    };

    stageKV(0);

    float o[16][4];
#pragma unroll
    for (int j = 0; j < 16; ++j)
#pragma unroll
        for (int qd = 0; qd < 4; ++qd) o[j][qd] = 0.f;
    float mr[2] = {-1e30f, -1e30f}, lr[2] = {0.f, 0.f};

    for (int iter = 0; iter < 32; ++iter) {
        asm volatile("cp.async.wait_group 0;" ::: "memory");
        __syncthreads();
        if (iter < 31) stageKV(iter + 1);

        const unsigned* kbuf = ks + (iter & 1) * 4352;
        const unsigned* vbuf = vs + (iter & 1) * 4096;

        float s[4][4];
#pragma unroll
        for (int j = 0; j < 4; ++j)
#pragma unroll
            for (int qd = 0; qd < 4; ++qd) s[j][qd] = 0.f;
#pragma unroll
        for (int kk = 0; kk < 8; ++kk) {
            uint2 lo0 = *(uint2*)&qlo[(wrow + g) * 72 + (kk * 4 + t) * 2];      // (p, p+4)
            uint2 lo1 = *(uint2*)&qlo[(wrow + g + 8) * 72 + (kk * 4 + t) * 2];
#pragma unroll
            for (int j = 0; j < 4; ++j) {
                const int kb2 = (8 * j + g) * 136 + kk * 16 + 2 * t;
                uint2 q0 = *(uint2*)&kbuf[kb2];
                uint2 q1 = *(uint2*)&kbuf[kb2 + 8];
                mma16(s[j], qh[kk][0], qh[kk][1], qh[kk][2], qh[kk][3], q0.x, q1.x);
                mma16(s[j], qh[kk][0], qh[kk][1], qh[kk][2], qh[kk][3], q0.y, q1.y);
                mma16(s[j], lo0.x, lo1.x, lo0.y, lo1.y, q0.x, q1.x);
            }
        }

#pragma unroll
        for (int r = 0; r < 2; ++r) {
            float tm = -1e30f;
#pragma unroll
            for (int j = 0; j < 4; ++j)
                tm = fmaxf(tm, fmaxf(s[j][2 * r], s[j][2 * r + 1]));
            tm = fmaxf(tm, __shfl_xor_sync(0xffffffffu, tm, 1));
            tm = fmaxf(tm, __shfl_xor_sync(0xffffffffu, tm, 2));
            const float mnew = fmaxf(mr[r], tm);
            const float scale = __expf(mr[r] - mnew);
            float sum = 0.f;
#pragma unroll
            for (int j = 0; j < 4; ++j) {
                float e0 = __expf(s[j][2 * r] - mnew);
                float e1 = __expf(s[j][2 * r + 1] - mnew);
                s[j][2 * r] = e0; s[j][2 * r + 1] = e1;
                sum += e0 + e1;
            }
            sum += __shfl_xor_sync(0xffffffffu, sum, 1);
            sum += __shfl_xor_sync(0xffffffffu, sum, 2);
            lr[r] = lr[r] * scale + sum;
            const bool rescale = !__all_sync(0xffffffffu, mnew == mr[r]);
            mr[r] = mnew;
            if (rescale) {
#pragma unroll
                for (int jt = 0; jt < 16; ++jt) {
                    o[jt][2 * r] *= scale; o[jt][2 * r + 1] *= scale;
                }
            }
        }

        // O += P V (P direct from regs; sigma-permuted V layout)
#pragma unroll
        for (int kk = 0; kk < 4; ++kk) {
            unsigned a0 = ftf(s[kk][0]);
            unsigned a1 = ftf(s[kk][2]);
            unsigned a2 = ftf(s[kk][1]);
            unsigned a3 = ftf(s[kk][3]);
#pragma unroll
            for (int j = 0; j < 16; ++j) {
                uint2 bp = *(uint2*)&vbuf[kk * 1024 + (8 * j + g) * 8 + t * 2];
                mma8(o[j], a0, a1, a2, a3, bp.x, bp.y);
            }
        }
    }

    const float inv0 = 1.f / lr[0], inv1 = 1.f / lr[1];
    unsigned* yb = y + (size_t)b * HWN * CI;
#pragma unroll
    for (int j = 0; j < 16; ++j) {
        const int col = 8 * j + 2 * t;
        unsigned hi, lo;
        split_pair(o[j][0] * inv0, o[j][1] * inv0, hi, lo);
        *(uint2*)&yb[(size_t)(n0 + wrow + g) * CI + col] = make_uint2(hi, lo);
        split_pair(o[j][2] * inv1, o[j][3] * inv1, hi, lo);
        *(uint2*)&yb[(size_t)(n0 + wrow + g + 8) * CI + col] = make_uint2(hi, lo);
    }
}

// ---- BN reduce ----
__global__ __launch_bounds__(256) void bnred_k(const float* __restrict__ inp0,
                                               float* __restrict__ out, int off) {
    __shared__ double rs[256], rs2[256];
    const int c = blockIdx.x, t = threadIdx.x;
    rs[t]  = (double)d_bnp[0][t][c] + (double)d_bnp[0][t + 256][c];
    rs2[t] = (double)d_bnp[1][t][c] + (double)d_bnp[1][t + 256][c];
    __syncthreads();
    for (int o = 128; o; o >>= 1) {
        if (t < o) { rs[t] += rs[t + o]; rs2[t] += rs2[t + o]; }
        __syncthreads();
    }
    if (t == 0) {
        const double cnt = (double)(BB * HWN);
        const double mean = rs[0] / cnt;
        const double var = rs2[0] / cnt - mean * mean;
        d_mean[c] = (float)mean;
        d_rstd[c] = (float)rsqrt(var + 1e-5);
        if (c == 0 && off == 1) out[0] = inp0[0];
    }
}

// ---- BN apply + residual ----
__global__ __launch_bounds__(256) void final_ew(const float* __restrict__ wyT,
                                                const float* __restrict__ x,
                                                const float* __restrict__ gamma,
                                                const float* __restrict__ beta,
                                                float* __restrict__ out, int off) {
    const int gi = blockIdx.x * 256 + threadIdx.x;
    const size_t base = (size_t)gi * 4;
    const int co = (int)((base >> 12) & 255);
    const float a = d_rstd[co] * gamma[co];
    const float bb = beta[co] - d_mean[co] * a;
    float4 wv = *(const float4*)&wyT[base];
    float4 xv = *(const float4*)&x[base];
    float* o = out + off + base;
    o[0] = wv.x * a + bb + xv.x;
    o[1] = wv.y * a + bb + xv.y;
    o[2] = wv.z * a + bb + xv.z;
    o[3] = wv.w * a + bb + xv.w;
}

extern "C" void kernel_launch(void* const* d_in, const int* in_sizes, int n_in,
                              void* d_out, int out_size) {
    const float* inp0 = (const float*)d_in[0];
    const float* x    = (const float*)d_in[1];
    const float* g_w  = (const float*)d_in[2];
    const float* g_b  = (const float*)d_in[3];
    const float* th_w = (const float*)d_in[4];
    const float* th_b = (const float*)d_in[5];
    const float* ph_w = (const float*)d_in[6];
    const float* ph_b = (const float*)d_in[7];
    const float* W_w  = (const float*)d_in[8];
    const float* W_b  = (const float*)d_in[9];
    const float* gam  = (const float*)d_in[10];
    const float* bet  = (const float*)d_in[11];
    float* out = (float*)d_out;

    float* p_wyT;
    unsigned *p_xts, *p_qp, *p_kp, *p_vp, *p_yp, *p_wth, *p_wph, *p_wg, *p_ww;
    cudaGetSymbolAddress((void**)&p_xts, d_xts);
    cudaGetSymbolAddress((void**)&p_qp, d_qpack);
    cudaGetSymbolAddress((void**)&p_kp, d_kpack);
    cudaGetSymbolAddress((void**)&p_vp, d_vpack);
    cudaGetSymbolAddress((void**)&p_yp, d_ypack);
    cudaGetSymbolAddress((void**)&p_wyT, d_wyT);
    cudaGetSymbolAddress((void**)&p_wth, d_wth);
    cudaGetSymbolAddress((void**)&p_wph, d_wph);
    cudaGetSymbolAddress((void**)&p_wg, d_wg);
    cudaGetSymbolAddress((void**)&p_ww, d_ww);

    const int GEMM2_SMEM = 4 * 5120 * 4;     // 81920
    const int ATTN_SMEM  = 26112 * 4;        // 104448
    cudaFuncSetAttribute(conv3_k, cudaFuncAttributeMaxDynamicSharedMemorySize, GEMM2_SMEM);
    cudaFuncSetAttribute(wconv_k, cudaFuncAttributeMaxDynamicSharedMemorySize, GEMM2_SMEM);
    cudaFuncSetAttribute(attn_k,  cudaFuncAttributeMaxDynamicSharedMemorySize, ATTN_SMEM);

    transpose_pack_k<<<dim3(HWN / 32, CC / 32, BB), 256>>>(x, p_xts);
    pack_w4_k<<<256, 256>>>(th_w, ph_w, g_w, W_w, p_wth, p_wph, p_wg, p_ww);

    conv3_k<<<dim3(32, 3, BB), 256, GEMM2_SMEM>>>(
        p_xts, p_wth, p_wph, p_wg, th_b, ph_b, g_b, p_qp, p_kp, p_vp);

    attn_k<<<dim3(HWN / 128, BB), 256, ATTN_SMEM>>>(p_qp, p_kp, p_vp, p_yp);

    wconv_k<<<dim3(32, 2, BB), 256, GEMM2_SMEM>>>(p_yp, p_ww, W_b, p_wyT);

    const int total = BB * CC * HWN;
    const int off = (out_size > total) ? (out_size - total) : 0;
    bnred_k<<<256, 256>>>(inp0, out, off);

    final_ew<<<total / 4 / 256, 256>>>(p_wyT, x, gam, bet, out, off);
}

// round 17
// speedup vs baseline: 1.0110x; 1.0110x over previous
#include <cuda_runtime.h>
#include <cuda_bf16.h>
#include <math.h>

#define BB   16
#define CC   256
#define CI   128
#define HWN  4096
#define NP   1024

__device__ unsigned d_xts[BB * HWN * CC];
__device__ unsigned d_qpack[BB * HWN * CI];
__device__ unsigned d_kpack[BB * NP * 128];
__device__ unsigned d_vpack[BB * NP * 128];
__device__ unsigned d_ypack[BB * HWN * CI];
__device__ float    d_wyT[BB * CC * HWN];
__device__ unsigned d_wth[CI * CC];
__device__ unsigned d_wph[CI * CC];
__device__ unsigned d_wg[CI * CC];
__device__ unsigned d_ww[CC * CI];
__device__ float d_bnp[2][512][256];
__device__ float d_mean[CC];
__device__ float d_rstd[CC];

__device__ __forceinline__ unsigned ftf(float x) {
    unsigned u; asm("cvt.rna.tf32.f32 %0,%1;" : "=r"(u) : "f"(x)); return u;
}
__device__ __forceinline__ void mma8(float* c, unsigned a0, unsigned a1, unsigned a2, unsigned a3,
                                     unsigned b0, unsigned b1) {
    asm volatile("mma.sync.aligned.m16n8k8.row.col.f32.tf32.tf32.f32 "
                 "{%0,%1,%2,%3},{%4,%5,%6,%7},{%8,%9},{%0,%1,%2,%3};"
                 : "+f"(c[0]), "+f"(c[1]), "+f"(c[2]), "+f"(c[3])
                 : "r"(a0), "r"(a1), "r"(a2), "r"(a3), "r"(b0), "r"(b1));
}
__device__ __forceinline__ void mma16(float* c, unsigned a0, unsigned a1, unsigned a2, unsigned a3,
                                      unsigned b0, unsigned b1) {
    asm volatile("mma.sync.aligned.m16n8k16.row.col.f32.bf16.bf16.f32 "
                 "{%0,%1,%2,%3},{%4,%5,%6,%7},{%8,%9},{%0,%1,%2,%3};"
                 : "+f"(c[0]), "+f"(c[1]), "+f"(c[2]), "+f"(c[3])
                 : "r"(a0), "r"(a1), "r"(a2), "r"(a3), "r"(b0), "r"(b1));
}
__device__ __forceinline__ void split_pair(float a, float b, unsigned &hi, unsigned &lo) {
    __nv_bfloat16 ha = __float2bfloat16_rn(a), hb = __float2bfloat16_rn(b);
    float ra = a - __bfloat162float(ha), rb = b - __bfloat162float(hb);
    __nv_bfloat162 hv; hv.x = ha; hv.y = hb;
    __nv_bfloat162 lv; lv.x = __float2bfloat16_rn(ra); lv.y = __float2bfloat16_rn(rb);
    hi = *(unsigned*)&hv; lo = *(unsigned*)&lv;
}
__device__ __forceinline__ unsigned s2u(const void* p) {
    return (unsigned)__cvta_generic_to_shared(p);
}
__device__ __forceinline__ void cp16(unsigned dst, const void* src) {
    asm volatile("cp.async.cg.shared.global [%0], [%1], 16;" :: "r"(dst), "l"(src) : "memory");
}

// ---- x[b][c][n] -> packed split-bf16, layout [b][n][c] ----
__global__ __launch_bounds__(256) void transpose_pack_k(const float* __restrict__ x,
                                                        unsigned* __restrict__ xts) {
    __shared__ float tl[32][33];
    const int b = blockIdx.z, c0 = blockIdx.y * 32, n0 = blockIdx.x * 32;
    const int tx = threadIdx.x & 31, ty = threadIdx.x >> 5;
    const float* xb = x + (size_t)b * CC * HWN;
#pragma unroll
    for (int i = 0; i < 4; ++i)
        tl[ty + 8 * i][tx] = xb[(size_t)(c0 + ty + 8 * i) * HWN + n0 + tx];
    __syncthreads();
    unsigned* xso = xts + (size_t)b * HWN * CC;
#pragma unroll
    for (int rep = 0; rep < 2; ++rep) {
        const int task = threadIdx.x + rep * 256;
        const int nl = task >> 4, p = task & 15;
        float f0 = tl[2 * p][nl], f1 = tl[2 * p + 1][nl];
        unsigned hi, lo;
        split_pair(f0, f1, hi, lo);
        *(uint2*)&xso[(size_t)(n0 + nl) * CC + c0 + 2 * p] = make_uint2(hi, lo);
    }
}

// ---- pack all 4 weight matrices ----
__global__ __launch_bounds__(256) void pack_w4_k(const float* __restrict__ w0,
                                                 const float* __restrict__ w1,
                                                 const float* __restrict__ w2,
                                                 const float* __restrict__ w3,
                                                 unsigned* __restrict__ o0,
                                                 unsigned* __restrict__ o1,
                                                 unsigned* __restrict__ o2,
                                                 unsigned* __restrict__ o3) {
    const int id = blockIdx.x * 256 + threadIdx.x;
    const int seg = id >> 14, loc = id & 16383;
    const float* s = (seg == 0) ? w0 : (seg == 1) ? w1 : (seg == 2) ? w2 : w3;
    unsigned* d = (seg == 0) ? o0 : (seg == 1) ? o1 : (seg == 2) ? o2 : o3;
    float2 v = *(const float2*)&s[2 * loc];
    unsigned hi, lo;
    split_pair(v.x, v.y, hi, lo);
    *(uint2*)&d[2 * loc] = make_uint2(hi, lo);
}

// ---- merged input convs: blockIdx.y = 0(theta),1(phi->kpack),2(g->vpack) ----
__global__ __launch_bounds__(256) void conv3_k(const unsigned* __restrict__ A,
                                               const unsigned* __restrict__ wq,
                                               const unsigned* __restrict__ wk,
                                               const unsigned* __restrict__ wv,
                                               const float* __restrict__ bq,
                                               const float* __restrict__ bk,
                                               const float* __restrict__ bv,
                                               unsigned* __restrict__ outq,
                                               unsigned* __restrict__ outk,
                                               unsigned* __restrict__ outv) {
    extern __shared__ unsigned smu[];
    unsigned* Abuf = smu;               // 2 x 128 x 40
    unsigned* Bbuf = smu + 2 * 5120;
    const int K = 256;
    const int b = blockIdx.z, mode = blockIdx.y;
    const int row0 = blockIdx.x * 128;
    const int tid = threadIdx.x, lane = tid & 31, wid = tid >> 5;
    const int g = lane >> 2, t = lane & 3;
    const int wm = (wid & 3) * 32, wn = (wid >> 2) * 64;
    const unsigned* Ag = A + (size_t)b * HWN * CC + (size_t)row0 * K;
    const unsigned* Bg = (mode == 0) ? wq : (mode == 1) ? wk : wv;
    const float* bias = (mode == 0) ? bq : (mode == 1) ? bk : bv;

    const unsigned aBase = s2u(Abuf), bBase = s2u(Bbuf);
    auto stage = [&](int c) {
        const unsigned ab = aBase + (unsigned)((c & 1) * 5120 * 4);
        const unsigned bb = bBase + (unsigned)((c & 1) * 5120 * 4);
        const unsigned* Ac = Ag + c * 32;
        const unsigned* Bc = Bg + c * 32;
#pragma unroll
        for (int i = 0; i < 4; ++i) {
            const int id = tid + i * 256;
            const int row = id >> 3, q = id & 7;
            cp16(ab + (unsigned)((row * 40 + q * 4) * 4), Ac + (size_t)row * K + q * 4);
            cp16(bb + (unsigned)((row * 40 + q * 4) * 4), Bc + (size_t)row * K + q * 4);
        }
        asm volatile("cp.async.commit_group;" ::: "memory");
    };

    float acc[2][8][4];
#pragma unroll
    for (int mt = 0; mt < 2; ++mt)
#pragma unroll
        for (int j = 0; j < 8; ++j)
#pragma unroll
            for (int q = 0; q < 4; ++q) acc[mt][j][q] = 0.f;

    stage(0);
    for (int c = 0; c < 8; ++c) {
        if (c + 1 < 8) {
            stage(c + 1);
            asm volatile("cp.async.wait_group 1;" ::: "memory");
        } else {
            asm volatile("cp.async.wait_group 0;" ::: "memory");
        }
        __syncthreads();
        const unsigned* Asu = Abuf + (c & 1) * 5120;
        const unsigned* Bsu = Bbuf + (c & 1) * 5120;
#pragma unroll
        for (int kk = 0; kk < 2; ++kk) {
            unsigned ah[2][4], al[2][4];
#pragma unroll
            for (int mt = 0; mt < 2; ++mt) {
                const int rb = (wm + mt * 16 + g) * 40 + kk * 16 + 2 * t;
                uint2 p0 = *(uint2*)&Asu[rb];
                uint2 p1 = *(uint2*)&Asu[rb + 8 * 40];
                uint2 p2 = *(uint2*)&Asu[rb + 8];
                uint2 p3 = *(uint2*)&Asu[rb + 8 * 40 + 8];
                ah[mt][0] = p0.x; al[mt][0] = p0.y;
                ah[mt][1] = p1.x; al[mt][1] = p1.y;
                ah[mt][2] = p2.x; al[mt][2] = p2.y;
                ah[mt][3] = p3.x; al[mt][3] = p3.y;
            }
#pragma unroll
            for (int j = 0; j < 8; ++j) {
                const int nb = (wn + 8 * j + g) * 40 + kk * 16 + 2 * t;
                uint2 q0 = *(uint2*)&Bsu[nb];
                uint2 q1 = *(uint2*)&Bsu[nb + 8];
#pragma unroll
                for (int mt = 0; mt < 2; ++mt) {
                    mma16(acc[mt][j], ah[mt][0], ah[mt][1], ah[mt][2], ah[mt][3], q0.x, q1.x);
                    mma16(acc[mt][j], ah[mt][0], ah[mt][1], ah[mt][2], ah[mt][3], q0.y, q1.y);
                    mma16(acc[mt][j], al[mt][0], al[mt][1], al[mt][2], al[mt][3], q0.x, q1.x);
                }
            }
        }
        __syncthreads();
    }

    if (mode == 0) {
        unsigned* Cp = outq + (size_t)b * HWN * CI;
#pragma unroll
        for (int mt = 0; mt < 2; ++mt)
#pragma unroll
            for (int j = 0; j < 8; ++j) {
                const int col = wn + 8 * j + 2 * t;
                float2 bvv = *(const float2*)&bias[col];
                const int r = row0 + wm + mt * 16 + g;
                unsigned hi, lo;
                split_pair(acc[mt][j][0] + bvv.x, acc[mt][j][1] + bvv.y, hi, lo);
                *(uint2*)&Cp[(size_t)r * CI + col] = make_uint2(hi, lo);
                split_pair(acc[mt][j][2] + bvv.x, acc[mt][j][3] + bvv.y, hi, lo);
                *(uint2*)&Cp[(size_t)(r + 8) * CI + col] = make_uint2(hi, lo);
            }
    } else {
        float* ts = (float*)smu;          // pitch 136
#pragma unroll
        for (int mt = 0; mt < 2; ++mt)
#pragma unroll
            for (int j = 0; j < 8; ++j) {
                const int cl = wn + 8 * j + 2 * t;
                float2 bvv = *(const float2*)&bias[cl];
                float* r0p = &ts[(wm + mt * 16 + g) * 136 + cl];
                r0p[0] = acc[mt][j][0] + bvv.x;  r0p[1] = acc[mt][j][1] + bvv.y;
                float* r1p = r0p + 8 * 136;
                r1p[0] = acc[mt][j][2] + bvv.x;  r1p[1] = acc[mt][j][3] + bvv.y;
            }
        __syncthreads();
        const int ph = blockIdx.x;
        unsigned* Op = (mode == 1) ? outk : outv;
#pragma unroll
        for (int rep = 0; rep < 4; ++rep) {
            const int task = tid + rep * 256;
            const int mloc = task >> 5, kq = task & 31;
            const float* t0 = &ts[(2 * mloc) * 136 + kq * 4];
            float4 v0 = *(const float4*)t0;
            float4 v1 = *(const float4*)(t0 + 136);
            float4 v2 = *(const float4*)(t0 + 64 * 136);
            float4 v3 = *(const float4*)(t0 + 65 * 136);
            float4 rr;
            rr.x = fmaxf(fmaxf(v0.x, v1.x), fmaxf(v2.x, v3.x));
            rr.y = fmaxf(fmaxf(v0.y, v1.y), fmaxf(v2.y, v3.y));
            rr.z = fmaxf(fmaxf(v0.z, v1.z), fmaxf(v2.z, v3.z));
            rr.w = fmaxf(fmaxf(v0.w, v1.w), fmaxf(v2.w, v3.w));
            const int m = ph * 32 + mloc;
            if (mode == 1) {
                unsigned h0, l0, h1, l1;
                split_pair(rr.x, rr.y, h0, l0);
                split_pair(rr.z, rr.w, h1, l1);
                *(uint4*)&Op[((size_t)b * NP + m) * 128 + kq * 4] = make_uint4(h0, l0, h1, l1);
            } else {
                unsigned* ob = Op + (size_t)b * NP * 128;
                const int base = (m >> 3) * 1024 + kq * 32 + (m & 7);
                ob[base]      = ftf(rr.x);
                ob[base + 8]  = ftf(rr.y);
                ob[base + 16] = ftf(rr.z);
                ob[base + 24] = ftf(rr.w);
            }
        }
    }
}

// ---- W conv: K=128, transposed store + BN partials ----
__global__ __launch_bounds__(256) void wconv_k(const unsigned* __restrict__ A,
                                               const unsigned* __restrict__ B,
                                               const float* __restrict__ bias,
                                               float* __restrict__ C) {
    extern __shared__ unsigned smu[];
    unsigned* Abuf = smu;
    unsigned* Bbuf = smu + 2 * 5120;
    const int K = 128;
    const int b = blockIdx.z;
    const int row0 = blockIdx.x * 128, col0 = blockIdx.y * 128;
    const int tid = threadIdx.x, lane = tid & 31, wid = tid >> 5;
    const int g = lane >> 2, t = lane & 3;
    const int wm = (wid & 3) * 32, wn = (wid >> 2) * 64;
    const unsigned* Ag = A + (size_t)b * HWN * CI + (size_t)row0 * K;
    const unsigned* Bg = B + (size_t)col0 * K;

    const unsigned aBase = s2u(Abuf), bBase = s2u(Bbuf);
    auto stage = [&](int c) {
        const unsigned ab = aBase + (unsigned)((c & 1) * 5120 * 4);
        const unsigned bb = bBase + (unsigned)((c & 1) * 5120 * 4);
        const unsigned* Ac = Ag + c * 32;
        const unsigned* Bc = Bg + c * 32;
#pragma unroll
        for (int i = 0; i < 4; ++i) {
            const int id = tid + i * 256;
            const int row = id >> 3, q = id & 7;
            cp16(ab + (unsigned)((row * 40 + q * 4) * 4), Ac + (size_t)row * K + q * 4);
            cp16(bb + (unsigned)((row * 40 + q * 4) * 4), Bc + (size_t)row * K + q * 4);
        }
        asm volatile("cp.async.commit_group;" ::: "memory");
    };

    float acc[2][8][4];
#pragma unroll
    for (int mt = 0; mt < 2; ++mt)
#pragma unroll
        for (int j = 0; j < 8; ++j)
#pragma unroll
            for (int q = 0; q < 4; ++q) acc[mt][j][q] = 0.f;

    stage(0);
    for (int c = 0; c < 4; ++c) {
        if (c + 1 < 4) {
            stage(c + 1);
            asm volatile("cp.async.wait_group 1;" ::: "memory");
        } else {
            asm volatile("cp.async.wait_group 0;" ::: "memory");
        }
        __syncthreads();
        const unsigned* Asu = Abuf + (c & 1) * 5120;
        const unsigned* Bsu = Bbuf + (c & 1) * 5120;
#pragma unroll
        for (int kk = 0; kk < 2; ++kk) {
            unsigned ah[2][4], al[2][4];
#pragma unroll
            for (int mt = 0; mt < 2; ++mt) {
                const int rb = (wm + mt * 16 + g) * 40 + kk * 16 + 2 * t;
                uint2 p0 = *(uint2*)&Asu[rb];
                uint2 p1 = *(uint2*)&Asu[rb + 8 * 40];
                uint2 p2 = *(uint2*)&Asu[rb + 8];
                uint2 p3 = *(uint2*)&Asu[rb + 8 * 40 + 8];
                ah[mt][0] = p0.x; al[mt][0] = p0.y;
                ah[mt][1] = p1.x; al[mt][1] = p1.y;
                ah[mt][2] = p2.x; al[mt][2] = p2.y;
                ah[mt][3] = p3.x; al[mt][3] = p3.y;
            }
#pragma unroll
            for (int j = 0; j < 8; ++j) {
                const int nb = (wn + 8 * j + g) * 40 + kk * 16 + 2 * t;
                uint2 q0 = *(uint2*)&Bsu[nb];
                uint2 q1 = *(uint2*)&Bsu[nb + 8];
#pragma unroll
                for (int mt = 0; mt < 2; ++mt) {
                    mma16(acc[mt][j], ah[mt][0], ah[mt][1], ah[mt][2], ah[mt][3], q0.x, q1.x);
                    mma16(acc[mt][j], ah[mt][0], ah[mt][1], ah[mt][2], ah[mt][3], q0.y, q1.y);
                    mma16(acc[mt][j], al[mt][0], al[mt][1], al[mt][2], al[mt][3], q0.x, q1.x);
                }
            }
        }
        __syncthreads();
    }

    float* ts = (float*)smu;    // pitch 136
    float sj[8][2], s2j[8][2];
#pragma unroll
    for (int j = 0; j < 8; ++j)
        sj[j][0] = sj[j][1] = s2j[j][0] = s2j[j][1] = 0.f;
#pragma unroll
    for (int mt = 0; mt < 2; ++mt)
#pragma unroll
        for (int j = 0; j < 8; ++j) {
            const int cl = wn + 8 * j + 2 * t;
            float2 bvv = *(const float2*)&bias[col0 + cl];
            const int nl = wm + mt * 16 + g;
            float v0 = acc[mt][j][0] + bvv.x, v1 = acc[mt][j][1] + bvv.y;
            float v2 = acc[mt][j][2] + bvv.x, v3 = acc[mt][j][3] + bvv.y;
            ts[cl * 136 + nl]           = v0;
            ts[(cl + 1) * 136 + nl]     = v1;
            ts[cl * 136 + nl + 8]       = v2;
            ts[(cl + 1) * 136 + nl + 8] = v3;
            sj[j][0] += v0 + v2;  sj[j][1] += v1 + v3;
            s2j[j][0] += v0 * v0 + v2 * v2;
            s2j[j][1] += v1 * v1 + v3 * v3;
        }
#pragma unroll
    for (int off = 4; off <= 16; off <<= 1)
#pragma unroll
        for (int j = 0; j < 8; ++j) {
            sj[j][0] += __shfl_xor_sync(0xffffffffu, sj[j][0], off);
            sj[j][1] += __shfl_xor_sync(0xffffffffu, sj[j][1], off);
            s2j[j][0] += __shfl_xor_sync(0xffffffffu, s2j[j][0], off);
            s2j[j][1] += __shfl_xor_sync(0xffffffffu, s2j[j][1], off);
        }
    __syncthreads();
    float* Ct = C + (size_t)b * CC * HWN;
#pragma unroll
    for (int rep = 0; rep < 16; ++rep) {
        const int task = tid + rep * 256;
        const int co = task >> 5, nq = task & 31;
        float4 v = *(const float4*)&ts[co * 136 + nq * 4];
        *(float4*)&Ct[(size_t)(col0 + co) * HWN + row0 + nq * 4] = v;
    }
    __syncthreads();
    float* partS = (float*)smu;
    float* partS2 = partS + 512;
    if (g == 0) {
#pragma unroll
        for (int j = 0; j < 8; ++j) {
            const int cbase = (wid & 3) * 128 + wn + 8 * j + 2 * t;
            partS[cbase] = sj[j][0];     partS[cbase + 1] = sj[j][1];
            partS2[cbase] = s2j[j][0];   partS2[cbase + 1] = s2j[j][1];
        }
    }
    __syncthreads();
    if (tid < 128) {
        const int c = tid;
        float s = partS[c] + partS[128 + c] + partS[256 + c] + partS[384 + c];
        float s2 = partS2[c] + partS2[128 + c] + partS2[256 + c] + partS2[384 + c];
        const int p = b * 32 + blockIdx.x;
        d_bnp[0][p][col0 + c] = s;
        d_bnp[1][p][col0 + c] = s2;
    }
}

// ---- fused attention: KT=32, 2 CTAs/SM, K+V double-buffered, P in regs (R15 layout) ----
__global__ __launch_bounds__(256, 2) void attn_k(const unsigned* __restrict__ qpk,
                                                 const unsigned* __restrict__ kpk,
                                                 const unsigned* __restrict__ vpk,
                                                 unsigned* __restrict__ y) {
    extern __shared__ float sm[];
    unsigned* ks  = (unsigned*)sm;       // 2 x 32 x 136
    unsigned* vs  = ks + 8704;           // 2 x 4096
    unsigned* qlo = vs + 8192;           // 128 x 68
    const int b = blockIdx.y, n0 = blockIdx.x * 128;
    const int tid = threadIdx.x, lane = tid & 31, wid = tid >> 5;
    const int g = lane >> 2, t = lane & 3;
    const int wrow = wid * 16;
    const unsigned* kg = kpk + (size_t)b * NP * 128;
    const unsigned* vg = vpk + (size_t)b * NP * 128;

    unsigned qh[8][4];
    {
        const unsigned* q0p = qpk + (size_t)b * HWN * CI + (size_t)(n0 + wrow + g) * CI;
        const unsigned* q1p = q0p + 8 * CI;
#pragma unroll
        for (int kk = 0; kk < 8; ++kk) {
            const int p = kk * 8 + t;
            uint2 u0 = *(const uint2*)&q0p[kk * 16 + 2 * t];
            uint2 u1 = *(const uint2*)&q1p[kk * 16 + 2 * t];
            uint2 u2 = *(const uint2*)&q0p[kk * 16 + 2 * t + 8];
            uint2 u3 = *(const uint2*)&q1p[kk * 16 + 2 * t + 8];
            qh[kk][0] = u0.x; qh[kk][1] = u1.x; qh[kk][2] = u2.x; qh[kk][3] = u3.x;
            qlo[(wrow + g) * 68 + p]         = u0.y;
            qlo[(wrow + g + 8) * 68 + p]     = u1.y;
            qlo[(wrow + g) * 68 + p + 4]     = u2.y;
            qlo[(wrow + g + 8) * 68 + p + 4] = u3.y;
        }
    }

    const unsigned ksBase = s2u(ks), vsBase = s2u(vs);
    auto stageKV = [&](int it) {
        const unsigned kb = ksBase + (unsigned)((it & 1) * 4352 * 4);
        const unsigned vb = vsBase + (unsigned)((it & 1) * 4096 * 4);
        const unsigned* kgt = kg + (size_t)it * 32 * 128;
        const unsigned* vgt = vg + (size_t)it * 4096;
#pragma unroll
        for (int i = 0; i < 4; ++i) {
            const int id = tid + i * 256;
            const int row = id >> 5, c = id & 31;
            cp16(kb + (unsigned)((row * 136 + c * 4) * 4), kgt + row * 128 + c * 4);
            cp16(vb + (unsigned)(id * 16), vgt + id * 4);
        }
        asm volatile("cp.async.commit_group;" ::: "memory");
    };

    stageKV(0);

    float o[16][4];
#pragma unroll
    for (int j = 0; j < 16; ++j)
#pragma unroll
        for (int qd = 0; qd < 4; ++qd) o[j][qd] = 0.f;
    float mr[2] = {-1e30f, -1e30f}, lr[2] = {0.f, 0.f};

    for (int iter = 0; iter < 32; ++iter) {
        asm volatile("cp.async.wait_group 0;" ::: "memory");
        __syncthreads();
        if (iter < 31) stageKV(iter + 1);

        const unsigned* kbuf = ks + (iter & 1) * 4352;
        const unsigned* vbuf = vs + (iter & 1) * 4096;

        float s[4][4];
#pragma unroll
        for (int j = 0; j < 4; ++j)
#pragma unroll
            for (int qd = 0; qd < 4; ++qd) s[j][qd] = 0.f;
#pragma unroll 4
        for (int kk = 0; kk < 8; ++kk) {
            const int p = kk * 8 + t;
            unsigned l0 = qlo[(wrow + g) * 68 + p];
            unsigned l1 = qlo[(wrow + g + 8) * 68 + p];
            unsigned l2 = qlo[(wrow + g) * 68 + p + 4];
            unsigned l3 = qlo[(wrow + g + 8) * 68 + p + 4];
#pragma unroll
            for (int j = 0; j < 4; ++j) {
                const int kb2 = (8 * j + g) * 136 + kk * 16 + 2 * t;
                uint2 q0 = *(uint2*)&kbuf[kb2];
                uint2 q1 = *(uint2*)&kbuf[kb2 + 8];
                mma16(s[j], qh[kk][0], qh[kk][1], qh[kk][2], qh[kk][3], q0.x, q1.x);
                mma16(s[j], qh[kk][0], qh[kk][1], qh[kk][2], qh[kk][3], q0.y, q1.y);
                mma16(s[j], l0, l1, l2, l3, q0.x, q1.x);
            }
        }

#pragma unroll
        for (int r = 0; r < 2; ++r) {
            float tm = -1e30f;
#pragma unroll
            for (int j = 0; j < 4; ++j)
                tm = fmaxf(tm, fmaxf(s[j][2 * r], s[j][2 * r + 1]));
            tm = fmaxf(tm, __shfl_xor_sync(0xffffffffu, tm, 1));
            tm = fmaxf(tm, __shfl_xor_sync(0xffffffffu, tm, 2));
            const float mnew = fmaxf(mr[r], tm);
            const float scale = __expf(mr[r] - mnew);
            float sum = 0.f;
#pragma unroll
            for (int j = 0; j < 4; ++j) {
                float e0 = __expf(s[j][2 * r] - mnew);
                float e1 = __expf(s[j][2 * r + 1] - mnew);
                s[j][2 * r] = e0; s[j][2 * r + 1] = e1;
                sum += e0 + e1;
            }
            sum += __shfl_xor_sync(0xffffffffu, sum, 1);
            sum += __shfl_xor_sync(0xffffffffu, sum, 2);
            lr[r] = lr[r] * scale + sum;
            const bool rescale = !__all_sync(0xffffffffu, mnew == mr[r]);
            mr[r] = mnew;
            if (rescale) {
#pragma unroll
                for (int jt = 0; jt < 16; ++jt) {
                    o[jt][2 * r] *= scale; o[jt][2 * r + 1] *= scale;
                }
            }
        }

        // O += P V (P direct from regs; sigma-permuted V layout)
#pragma unroll
        for (int kk = 0; kk < 4; ++kk) {
            unsigned a0 = ftf(s[kk][0]);
            unsigned a1 = ftf(s[kk][2]);
            unsigned a2 = ftf(s[kk][1]);
            unsigned a3 = ftf(s[kk][3]);
#pragma unroll
            for (int j = 0; j < 16; ++j) {
                uint2 bp = *(uint2*)&vbuf[kk * 1024 + (8 * j + g) * 8 + t * 2];
                mma8(o[j], a0, a1, a2, a3, bp.x, bp.y);
            }
        }
    }

    const float inv0 = 1.f / lr[0], inv1 = 1.f / lr[1];
    unsigned* yb = y + (size_t)b * HWN * CI;
#pragma unroll
    for (int j = 0; j < 16; ++j) {
        const int col = 8 * j + 2 * t;
        unsigned hi, lo;
        split_pair(o[j][0] * inv0, o[j][1] * inv0, hi, lo);
        *(uint2*)&yb[(size_t)(n0 + wrow + g) * CI + col] = make_uint2(hi, lo);
        split_pair(o[j][2] * inv1, o[j][3] * inv1, hi, lo);
        *(uint2*)&yb[(size_t)(n0 + wrow + g + 8) * CI + col] = make_uint2(hi, lo);
    }
}

// ---- BN reduce ----
__global__ __launch_bounds__(256) void bnred_k(const float* __restrict__ inp0,
                                               float* __restrict__ out, int off) {
    __shared__ double rs[256], rs2[256];
    const int c = blockIdx.x, t = threadIdx.x;
    rs[t]  = (double)d_bnp[0][t][c] + (double)d_bnp[0][t + 256][c];
    rs2[t] = (double)d_bnp[1][t][c] + (double)d_bnp[1][t + 256][c];
    __syncthreads();
    for (int o = 128; o; o >>= 1) {
        if (t < o) { rs[t] += rs[t + o]; rs2[t] += rs2[t + o]; }
        __syncthreads();
    }
    if (t == 0) {
        const double cnt = (double)(BB * HWN);
        const double mean = rs[0] / cnt;
        const double var = rs2[0] / cnt - mean * mean;
        d_mean[c] = (float)mean;
        d_rstd[c] = (float)rsqrt(var + 1e-5);
        if (c == 0 && off == 1) out[0] = inp0[0];
    }
}

// ---- BN apply + residual ----
__global__ __launch_bounds__(256) void final_ew(const float* __restrict__ wyT,
                                                const float* __restrict__ x,
                                                const float* __restrict__ gamma,
                                                const float* __restrict__ beta,
                                                float* __restrict__ out, int off) {
    const int gi = blockIdx.x * 256 + threadIdx.x;
    const size_t base = (size_t)gi * 4;
    const int co = (int)((base >> 12) & 255);
    const float a = d_rstd[co] * gamma[co];
    const float bb = beta[co] - d_mean[co] * a;
    float4 wv = *(const float4*)&wyT[base];
    float4 xv = *(const float4*)&x[base];
    float* o = out + off + base;
    o[0] = wv.x * a + bb + xv.x;
    o[1] = wv.y * a + bb + xv.y;
    o[2] = wv.z * a + bb + xv.z;
    o[3] = wv.w * a + bb + xv.w;
}

extern "C" void kernel_launch(void* const* d_in, const int* in_sizes, int n_in,
                              void* d_out, int out_size) {
    const float* inp0 = (const float*)d_in[0];
    const float* x    = (const float*)d_in[1];
    const float* g_w  = (const float*)d_in[2];
    const float* g_b  = (const float*)d_in[3];
    const float* th_w = (const float*)d_in[4];
    const float* th_b = (const float*)d_in[5];
    const float* ph_w = (const float*)d_in[6];
    const float* ph_b = (const float*)d_in[7];
    const float* W_w  = (const float*)d_in[8];
    const float* W_b  = (const float*)d_in[9];
    const float* gam  = (const float*)d_in[10];
    const float* bet  = (const float*)d_in[11];
    float* out = (float*)d_out;

    float* p_wyT;
    unsigned *p_xts, *p_qp, *p_kp, *p_vp, *p_yp, *p_wth, *p_wph, *p_wg, *p_ww;
    cudaGetSymbolAddress((void**)&p_xts, d_xts);
    cudaGetSymbolAddress((void**)&p_qp, d_qpack);
    cudaGetSymbolAddress((void**)&p_kp, d_kpack);
    cudaGetSymbolAddress((void**)&p_vp, d_vpack);
    cudaGetSymbolAddress((void**)&p_yp, d_ypack);
    cudaGetSymbolAddress((void**)&p_wyT, d_wyT);
    cudaGetSymbolAddress((void**)&p_wth, d_wth);
    cudaGetSymbolAddress((void**)&p_wph, d_wph);
    cudaGetSymbolAddress((void**)&p_wg, d_wg);
    cudaGetSymbolAddress((void**)&p_ww, d_ww);

    const int GEMM2_SMEM = 4 * 5120 * 4;     // 81920
    const int ATTN_SMEM  = 25600 * 4;        // 102400
    cudaFuncSetAttribute(conv3_k, cudaFuncAttributeMaxDynamicSharedMemorySize, GEMM2_SMEM);
    cudaFuncSetAttribute(wconv_k, cudaFuncAttributeMaxDynamicSharedMemorySize, GEMM2_SMEM);
    cudaFuncSetAttribute(attn_k,  cudaFuncAttributeMaxDynamicSharedMemorySize, ATTN_SMEM);

    transpose_pack_k<<<dim3(HWN / 32, CC / 32, BB), 256>>>(x, p_xts);
    pack_w4_k<<<256, 256>>>(th_w, ph_w, g_w, W_w, p_wth, p_wph, p_wg, p_ww);

    conv3_k<<<dim3(32, 3, BB), 256, GEMM2_SMEM>>>(
        p_xts, p_wth, p_wph, p_wg, th_b, ph_b, g_b, p_qp, p_kp, p_vp);

    attn_k<<<dim3(HWN / 128, BB), 256, ATTN_SMEM>>>(p_qp, p_kp, p_vp, p_yp);

    wconv_k<<<dim3(32, 2, BB), 256, GEMM2_SMEM>>>(p_yp, p_ww, W_b, p_wyT);

    const int total = BB * CC * HWN;
    const int off = (out_size > total) ? (out_size - total) : 0;
    bnred_k<<<256, 256>>>(inp0, out, off);

    final_ew<<<total / 4 / 256, 256>>>(p_wyT, x, gam, bet, out, off);
}